// round 2
// baseline (speedup 1.0000x reference)
#include <cuda_runtime.h>
#include <math.h>
#include <stdint.h>

// ---------------------------------------------------------------------------
// Problem constants
// ---------------------------------------------------------------------------
#define NB   64     // batch
#define CCH  64     // channels
#define TT   300    // time
#define VV   25     // vertices
#define SS   3      // subsets
#define IC   16     // inter channels
#define TV   (TT*VV)          // 7500
#define KROWS (IC*TT)         // 4800

// Scratch (device globals — no allocation allowed)
__device__ float g_t1[SS * NB * IC * TV];
__device__ float g_t2[SS * NB * IC * TV];
__device__ float g_A1[SS * NB * VV * VV];
__device__ float g_Afull[SS * VV * VV];

// ---------------------------------------------------------------------------
// K0: A_full = A + PA + (8A^4 - 4A^2 - 4A + I)
// ---------------------------------------------------------------------------
__global__ void k_afull(const float* __restrict__ A, const float* __restrict__ PA) {
    for (int idx = threadIdx.x; idx < SS * VV * VV; idx += blockDim.x) {
        int r = idx % (VV * VV);
        int v1 = r / VV, v2 = r % VV;
        float a = A[idx];
        float a2 = a * a;
        float ch = 8.f * a2 * a2 - 4.f * a2 - 4.f * a + (v1 == v2 ? 1.f : 0.f);
        g_Afull[idx] = a + PA[idx] + ch;
    }
}

// ---------------------------------------------------------------------------
// K1 (tensor-core rewrite): t1/t2 slim_conv as implicit-im2col GEMM, tf32 mma.
//   D[32, 384] = W[32, 576] @ B[576, 384]
//   rows 0..15 = conv1 (WT1) out-channels, 16..31 = conv2 (WT2)
//   K = ci*9 + dt (576);  points = 12 t x 32 v (v padded 25->32)
// grid (25, N, S), block 256 (8 warps, each warp: M=32 x N=48 = 6 n8-tiles)
// ---------------------------------------------------------------------------
#define TCH 12
#define XROWS 20          // TCH + 8
#define KTOT 576
#define KSTEPS 72
#define WPTS 48

__device__ __forceinline__ uint32_t f2tf32(float f) {
    uint32_t r;
    asm("cvt.rna.tf32.f32 %0, %1;" : "=r"(r) : "f"(f));
    return r;
}

__global__ __launch_bounds__(256, 1)
void k_conv_mma(const float* __restrict__ x,
                const float* __restrict__ WT1, const float* __restrict__ bT1,
                const float* __restrict__ WT2, const float* __restrict__ bT2,
                const float* __restrict__ weights) {
    extern __shared__ float sm[];
    float* xs  = sm;                  // 64 * 20 * 25 = 32000
    float* Wt  = sm + 32000;          // 576 * 33 = 19008 (padded stride 33)
    float* scb = Wt + 19008;          // sc[16], b1[16], b2[16]

    const int s  = blockIdx.z;
    const int n  = blockIdx.y;
    const int t0 = blockIdx.x * TCH;
    const int tid = threadIdx.x;

    // ---- stage W (both convs), tf32-rounded, layout Wt[k][co], stride 33 ----
    const float* W1g = WT1 + s * IC * CCH * 9;
    const float* W2g = WT2 + s * IC * CCH * 9;
    for (int i = tid; i < KTOT * 32; i += 256) {
        int k  = i >> 5;
        int co = i & 31;
        int ci = k / 9;
        int dt = k - ci * 9;
        float w = (co < 16) ? W1g[(co * CCH + ci) * 9 + dt]
                            : W2g[((co - 16) * CCH + ci) * 9 + dt];
        Wt[k * 33 + co] = __uint_as_float(f2tf32(w));
    }
    // ---- stage x tile with zero t-padding, tf32-rounded ----
    const float* xb = x + n * CCH * TV;
    for (int i = tid; i < CCH * XROWS * VV; i += 256) {
        int ci  = i / (XROWS * VV);
        int rr  = i - ci * (XROWS * VV);
        int row = rr / VV;
        int v   = rr - row * VV;
        int t   = t0 - 4 + row;
        float val = (t >= 0 && t < TT) ? xb[ci * TV + t * VV + v] : 0.f;
        xs[i] = __uint_as_float(f2tf32(val));
    }
    if (tid < 16) {
        float ws1 = weights[1], ws2 = weights[2], ws3 = weights[3], ws4 = weights[4];
        int co = tid;
        // slim splits for out_c=16: 9, 11, 12, 14
        float sc = (co < 9) ? 1.f : (co < 11) ? ws1 : (co < 12) ? ws2 : (co < 14) ? ws3 : ws4;
        scb[co]      = sc;
        scb[16 + co] = bT1[s * IC + co];
        scb[32 + co] = bT2[s * IC + co];
    }
    __syncthreads();

    const int warp = tid >> 5;
    const int lane = tid & 31;
    const int g  = lane >> 2;    // group id
    const int tg = lane & 3;     // thread-in-group
    const int pbase = warp * WPTS;

    float d[2][6][4];
#pragma unroll
    for (int m = 0; m < 2; m++)
#pragma unroll
        for (int nt = 0; nt < 6; nt++)
#pragma unroll
            for (int q = 0; q < 4; q++) d[m][nt][q] = 0.f;

    // per-ntile B-source offsets (point for this lane: n-index = g)
    int  pofs[6];
    bool pval[6];
#pragma unroll
    for (int nt = 0; nt < 6; nt++) {
        int p  = pbase + nt * 8 + g;
        int tl = p >> 5;
        int v  = p & 31;
        pval[nt] = (v < VV);
        pofs[nt] = tl * VV + (pval[nt] ? v : 0);
    }

    for (int ks = 0; ks < KSTEPS; ks++) {
        int k0 = ks * 8 + tg;
        int k1 = k0 + 4;
        // A fragments (W)
        const float* w0 = Wt + k0 * 33;
        const float* w1 = Wt + k1 * 33;
        uint32_t a0[4], a1[4];
        a0[0] = __float_as_uint(w0[g]);
        a0[1] = __float_as_uint(w0[g + 8]);
        a0[2] = __float_as_uint(w1[g]);
        a0[3] = __float_as_uint(w1[g + 8]);
        a1[0] = __float_as_uint(w0[16 + g]);
        a1[1] = __float_as_uint(w0[16 + g + 8]);
        a1[2] = __float_as_uint(w1[16 + g]);
        a1[3] = __float_as_uint(w1[16 + g + 8]);
        // B row source offsets
        int ci0 = k0 / 9, dt0 = k0 - ci0 * 9;
        int ci1 = k1 / 9, dt1 = k1 - ci1 * 9;
        int xo0 = ci0 * (XROWS * VV) + dt0 * VV;
        int xo1 = ci1 * (XROWS * VV) + dt1 * VV;
#pragma unroll
        for (int nt = 0; nt < 6; nt++) {
            uint32_t b0 = pval[nt] ? __float_as_uint(xs[xo0 + pofs[nt]]) : 0u;
            uint32_t b1 = pval[nt] ? __float_as_uint(xs[xo1 + pofs[nt]]) : 0u;
            asm volatile(
                "mma.sync.aligned.m16n8k8.row.col.f32.tf32.tf32.f32 "
                "{%0,%1,%2,%3}, {%4,%5,%6,%7}, {%8,%9}, {%0,%1,%2,%3};"
                : "+f"(d[0][nt][0]), "+f"(d[0][nt][1]), "+f"(d[0][nt][2]), "+f"(d[0][nt][3])
                : "r"(a0[0]), "r"(a0[1]), "r"(a0[2]), "r"(a0[3]), "r"(b0), "r"(b1));
            asm volatile(
                "mma.sync.aligned.m16n8k8.row.col.f32.tf32.tf32.f32 "
                "{%0,%1,%2,%3}, {%4,%5,%6,%7}, {%8,%9}, {%0,%1,%2,%3};"
                : "+f"(d[1][nt][0]), "+f"(d[1][nt][1]), "+f"(d[1][nt][2]), "+f"(d[1][nt][3])
                : "r"(a1[0]), "r"(a1[1]), "r"(a1[2]), "r"(a1[3]), "r"(b0), "r"(b1));
        }
    }

    // ---- epilogue: scale + bias, store to g_t1 / g_t2 ----
    const size_t obase = (size_t)(s * NB + n) * IC * TV;
#pragma unroll
    for (int mt = 0; mt < 2; mt++) {
        float* gout = mt == 0 ? g_t1 : g_t2;
        const float* bb = scb + 16 + mt * 16;
#pragma unroll
        for (int nt = 0; nt < 6; nt++) {
            int p0 = pbase + nt * 8 + tg * 2;
            int p1 = p0 + 1;
            int v0 = p0 & 31, tl0 = p0 >> 5;
            int v1 = p1 & 31, tl1 = p1 >> 5;
            int coA = g, coB = g + 8;
            float sA = scb[coA], sB = scb[coB];
            float bA = bb[coA],  bB = bb[coB];
            if (v0 < VV) {
                size_t o = obase + (size_t)coA * TV + (t0 + tl0) * VV + v0;
                gout[o] = sA * (d[mt][nt][0] + bA);
                o = obase + (size_t)coB * TV + (t0 + tl0) * VV + v0;
                gout[o] = sB * (d[mt][nt][2] + bB);
            }
            if (v1 < VV) {
                size_t o = obase + (size_t)coA * TV + (t0 + tl1) * VV + v1;
                gout[o] = sA * (d[mt][nt][1] + bA);
                o = obase + (size_t)coB * TV + (t0 + tl1) * VV + v1;
                gout[o] = sB * (d[mt][nt][3] + bB);
            }
        }
    }
}

// ---------------------------------------------------------------------------
// K2: attention logits + softmax(axis=-2 over v1) + A_full -> A1  (unchanged)
// ---------------------------------------------------------------------------
__global__ __launch_bounds__(640, 2)
void k_att() {
    const int n = blockIdx.x;
    const int s = blockIdx.y;
    __shared__ float s1[64 * VV];
    __shared__ float s2[64 * VV];
    __shared__ float sl[VV * VV];

    const float* t1b = g_t1 + (size_t)(s * NB + n) * IC * TV;
    const float* t2b = g_t2 + (size_t)(s * NB + n) * IC * TV;

    const int tid = threadIdx.x;
    const int v1 = tid / 25;
    const int v2 = tid - v1 * 25;
    const bool act = tid < VV * VV;
    float acc = 0.f;

    for (int ch = 0; ch < KROWS / 64; ch++) {
        for (int idx = tid; idx < 64 * VV; idx += 640) {
            int row = idx / VV, vv = idx - row * VV;
            int cr = ch * 64 + row;
            int c = cr / TT, t = cr - c * TT;
            int off = c * TV + t * VV + vv;
            s1[idx] = t1b[off];
            s2[idx] = t2b[off];
        }
        __syncthreads();
        if (act) {
#pragma unroll 8
            for (int k = 0; k < 64; k++)
                acc += s1[k * VV + v1] * s2[k * VV + v2];
        }
        __syncthreads();
    }

    if (act) sl[tid] = acc * (1.0f / (float)KROWS);
    __syncthreads();

    if (tid < VV) {
        const int c2 = tid;
        float m = -1e30f;
#pragma unroll
        for (int r = 0; r < VV; r++) m = fmaxf(m, sl[r * VV + c2]);
        float sum = 0.f;
#pragma unroll
        for (int r = 0; r < VV; r++) sum += expf(sl[r * VV + c2] - m);
        float inv = 1.f / sum;
        const float* af = g_Afull + s * VV * VV;
        float* a1o = g_A1 + (size_t)(s * NB + n) * VV * VV;
#pragma unroll
        for (int r = 0; r < VV; r++)
            a1o[r * VV + c2] = af[r * VV + c2] + expf(sl[r * VV + c2] - m) * inv;
    }
}

// ---------------------------------------------------------------------------
// K3: agg + Wd fold + BN + residual + relu (unchanged)
// ---------------------------------------------------------------------------
#define TT2 10
__global__ __launch_bounds__(256, 2)
void k_aggz(const float* __restrict__ x,
            const float* __restrict__ Wd, const float* __restrict__ bd,
            const float* __restrict__ weights,
            const float* __restrict__ bng, const float* __restrict__ bnb,
            const float* __restrict__ bnm, const float* __restrict__ bnv,
            float* __restrict__ out) {
    extern __shared__ float sm[];
    float* xs  = sm;              // 250*68 = 17000
    float* WdT = xs + 17000;      // 4096
    float* A1s = WdT + 4096;      // 625
    float* ka  = A1s + 625;       // 64
    float* kb  = ka + 64;         // 64

    const int n  = blockIdx.y;
    const int t0 = blockIdx.x * TT2;
    const int tid = threadIdx.x;
    const int nb = n * CCH * TV;

    for (int idx = tid; idx < CCH * TT2 * VV; idx += 256) {
        int ci = idx / (TT2 * VV);
        int tv = idx - ci * (TT2 * VV);
        xs[tv * 68 + ci] = x[nb + ci * TV + t0 * VV + tv];
    }
    if (tid < CCH) {
        int co = tid;
        float ws1 = weights[1], ws2 = weights[2], ws3 = weights[3], ws4 = weights[4];
        float sc = (co < 38) ? 1.f : (co < 44) ? ws1 : (co < 51) ? ws2 : (co < 57) ? ws3 : ws4;
        float bdsum = bd[co] + bd[CCH + co] + bd[2 * CCH + co];
        float fa = bng[co] * rsqrtf(bnv[co] + 1e-5f);
        ka[co] = fa * sc;
        kb[co] = fa * sc * bdsum + bnb[co] - bnm[co] * fa;
    }

    float zacc[64];
#pragma unroll
    for (int i = 0; i < 64; i++) zacc[i] = 0.f;

    const int tv = tid;
    const bool act = tid < TT2 * VV;
    const int tloc = tv / 25;
    const int v2 = tv - tloc * 25;

    for (int s = 0; s < SS; s++) {
        __syncthreads();
        for (int idx = tid; idx < CCH * CCH; idx += 256) {
            int ci = idx >> 6;
            int co = idx & 63;
            WdT[ci * 64 + co] = Wd[(s * CCH + co) * CCH + ci];
        }
        for (int idx = tid; idx < VV * VV; idx += 256)
            A1s[idx] = g_A1[(size_t)(s * NB + n) * VV * VV + idx];
        __syncthreads();

        if (act) {
#pragma unroll
            for (int cb = 0; cb < 64; cb += 16) {
                float a[16];
#pragma unroll
                for (int i = 0; i < 16; i++) a[i] = 0.f;
#pragma unroll
                for (int vv1 = 0; vv1 < VV; vv1++) {
                    float aw = A1s[vv1 * VV + v2];
                    const float4* xp = (const float4*)(xs + (tloc * 25 + vv1) * 68 + cb);
#pragma unroll
                    for (int q = 0; q < 4; q++) {
                        float4 xv = xp[q];
                        a[4*q+0] += xv.x * aw; a[4*q+1] += xv.y * aw;
                        a[4*q+2] += xv.z * aw; a[4*q+3] += xv.w * aw;
                    }
                }
#pragma unroll
                for (int ci = 0; ci < 16; ci++) {
                    float av = a[ci];
                    const float4* wp = (const float4*)(WdT + (cb + ci) * 64);
#pragma unroll
                    for (int q = 0; q < 16; q++) {
                        float4 wv = wp[q];
                        zacc[4*q+0] += wv.x * av; zacc[4*q+1] += wv.y * av;
                        zacc[4*q+2] += wv.z * av; zacc[4*q+3] += wv.w * av;
                    }
                }
            }
        }
    }

    if (act) {
        const float* xrow = xs + (tloc * 25 + v2) * 68;
        const int ob = nb + t0 * VV + tv;
#pragma unroll
        for (int co = 0; co < CCH; co++) {
            float val = ka[co] * zacc[co] + kb[co] + xrow[co];
            out[ob + co * TV] = fmaxf(val, 0.f);
        }
    }
}

// ---------------------------------------------------------------------------
// launch
// ---------------------------------------------------------------------------
extern "C" void kernel_launch(void* const* d_in, const int* in_sizes, int n_in,
                              void* d_out, int out_size) {
    const float* x    = (const float*)d_in[0];
    const float* wts  = (const float*)d_in[1];
    const float* A    = (const float*)d_in[2];
    const float* PA   = (const float*)d_in[3];
    const float* Wd   = (const float*)d_in[4];
    const float* bd   = (const float*)d_in[5];
    const float* WT1  = (const float*)d_in[6];
    const float* bT1  = (const float*)d_in[7];
    const float* WT2  = (const float*)d_in[8];
    const float* bT2  = (const float*)d_in[9];
    const float* bng  = (const float*)d_in[10];
    const float* bnb  = (const float*)d_in[11];
    const float* bnm  = (const float*)d_in[12];
    const float* bnv  = (const float*)d_in[13];
    float* out = (float*)d_out;

    const int conv_smem = (32000 + 19008 + 48) * 4;       // 204224
    const int aggz_smem = (17000 + 4096 + 625 + 128) * 4; // 87396
    cudaFuncSetAttribute(k_conv_mma, cudaFuncAttributeMaxDynamicSharedMemorySize, conv_smem);
    cudaFuncSetAttribute(k_aggz, cudaFuncAttributeMaxDynamicSharedMemorySize, aggz_smem);

    k_afull<<<1, 640>>>(A, PA);
    k_conv_mma<<<dim3(TT / TCH, NB, SS), 256, conv_smem>>>(x, WT1, bT1, WT2, bT2, wts);
    k_att<<<dim3(NB, SS), 640>>>();
    k_aggz<<<dim3(TT / TT2, NB), 256, aggz_smem>>>(x, Wd, bd, wts, bng, bnb, bnm, bnv, out);
}

// round 4
// speedup vs baseline: 1.1646x; 1.1646x over previous
#include <cuda_runtime.h>
#include <math.h>
#include <stdint.h>

// ---------------------------------------------------------------------------
// Problem constants
// ---------------------------------------------------------------------------
#define NB   64     // batch
#define CCH  64     // channels
#define TT   300    // time
#define VV   25     // vertices
#define SS   3      // subsets
#define IC   16     // inter channels
#define TV   (TT*VV)          // 7500
#define KROWS (IC*TT)         // 4800

// Scratch (device globals — no allocation allowed)
__device__ float g_t1[SS * NB * IC * TV];
__device__ float g_t2[SS * NB * IC * TV];
__device__ float g_A1[SS * NB * VV * VV];
__device__ float g_Afull[SS * VV * VV];

// ---------------------------------------------------------------------------
// Packed fp32x2 helpers (SASS FFMA2 — only reachable via PTX fma.rn.f32x2)
// ---------------------------------------------------------------------------
__device__ __forceinline__ void fma2(uint64_t& d, uint64_t a, uint64_t b) {
    asm("fma.rn.f32x2 %0, %1, %2, %0;" : "+l"(d) : "l"(a), "l"(b));
}
__device__ __forceinline__ uint64_t pack2(float lo, float hi) {
    uint64_t r;
    asm("mov.b64 %0, {%1, %2};" : "=l"(r) : "f"(lo), "f"(hi));
    return r;
}
__device__ __forceinline__ float2 unpack2(uint64_t v) {
    float2 r;
    asm("mov.b64 {%0, %1}, %2;" : "=f"(r.x), "=f"(r.y) : "l"(v));
    return r;
}

// ---------------------------------------------------------------------------
// K0: A_full = A + PA + (8A^4 - 4A^2 - 4A + I)   (elementwise powers)
// ---------------------------------------------------------------------------
__global__ void k_afull(const float* __restrict__ A, const float* __restrict__ PA) {
    for (int idx = threadIdx.x; idx < SS * VV * VV; idx += blockDim.x) {
        int r = idx % (VV * VV);
        int v1 = r / VV, v2 = r % VV;
        float a = A[idx];
        float a2 = a * a;
        float ch = 8.f * a2 * a2 - 4.f * a2 - 4.f * a + (v1 == v2 ? 1.f : 0.f);
        g_Afull[idx] = a + PA[idx] + ch;
    }
}

// ---------------------------------------------------------------------------
// K1: t1/t2 = slim_conv(x, WT1/WT2, pad_t=4) for all subsets.  f32x2 inner.
// grid: (10, N, S), block: 416 (400 active = 16 t-pairs x 25 v)
// smem: W1,W2 as [ci][dt][co] float, co-pairs contiguous -> packed operands.
// ---------------------------------------------------------------------------
__global__ __launch_bounds__(416, 1)
void k_conv(const float* __restrict__ x,
            const float* __restrict__ WT1, const float* __restrict__ bT1,
            const float* __restrict__ WT2, const float* __restrict__ bT2,
            const float* __restrict__ weights) {
    const int s = blockIdx.z;
    const int n = blockIdx.y;
    extern __shared__ float sw[];
    float* sW1 = sw;            // 9216
    float* sW2 = sw + 9216;     // 9216

    const float* W1g = WT1 + s * IC * CCH * 9;
    const float* W2g = WT2 + s * IC * CCH * 9;
    for (int idx = threadIdx.x; idx < IC * CCH * 9; idx += 416) {
        int ci = idx / 144;
        int r = idx - ci * 144;
        int dt = r >> 4;
        int co = r & 15;
        int gidx = (co * CCH + ci) * 9 + dt;
        sW1[idx] = W1g[gidx];
        sW2[idx] = W2g[gidx];
    }
    __syncthreads();

    const int tid = threadIdx.x;
    if (tid >= 400) return;
    const int tp = tid / 25;
    const int v = tid - tp * 25;
    const int t0 = blockIdx.x * 32 + tp * 2;
    if (t0 >= TT) return;

    // packed accumulators: co-pairs (8 pairs = 16 co) x {t0,t1} x {conv1,conv2}
    uint64_t a10[8], a11[8], a20[8], a21[8];
    const uint64_t z2 = pack2(0.f, 0.f);
#pragma unroll
    for (int i = 0; i < 8; i++) { a10[i] = z2; a11[i] = z2; a20[i] = z2; a21[i] = z2; }

    const ulonglong2* w1f = (const ulonglong2*)sW1;   // (ci*9+dt)*4 + q
    const ulonglong2* w2f = (const ulonglong2*)sW2;
    const float* xb = x + n * CCH * TV + v;

    for (int ci = 0; ci < CCH; ci++) {
        const float* xp = xb + ci * TV;
        float xr[10];
#pragma unroll
        for (int k = 0; k < 10; k++) {
            int tt = t0 - 4 + k;
            xr[k] = (tt >= 0 && tt < TT) ? __ldg(xp + tt * VV) : 0.f;
        }
#pragma unroll
        for (int dt = 0; dt < 9; dt++) {
            uint64_t xp0 = pack2(xr[dt], xr[dt]);
            uint64_t xp1 = pack2(xr[dt + 1], xr[dt + 1]);
            const ulonglong2* wp1 = w1f + (ci * 9 + dt) * 4;
            const ulonglong2* wp2 = w2f + (ci * 9 + dt) * 4;
#pragma unroll
            for (int q = 0; q < 4; q++) {
                ulonglong2 w1v = wp1[q];
                ulonglong2 w2v = wp2[q];
                fma2(a10[2*q],   w1v.x, xp0);
                fma2(a10[2*q+1], w1v.y, xp0);
                fma2(a11[2*q],   w1v.x, xp1);
                fma2(a11[2*q+1], w1v.y, xp1);
                fma2(a20[2*q],   w2v.x, xp0);
                fma2(a20[2*q+1], w2v.y, xp0);
                fma2(a21[2*q],   w2v.x, xp1);
                fma2(a21[2*q+1], w2v.y, xp1);
            }
        }
    }

    const float ws1 = __ldg(weights + 1), ws2 = __ldg(weights + 2);
    const float ws3 = __ldg(weights + 3), ws4 = __ldg(weights + 4);
    const int base = ((s * NB + n) * IC) * TV + t0 * VV + v;
#pragma unroll
    for (int co = 0; co < IC; co++) {
        // slim splits for out_c=16: 9, 11, 12, 14
        float sc = (co < 9) ? 1.f : (co < 11) ? ws1 : (co < 12) ? ws2 : (co < 14) ? ws3 : ws4;
        float b1 = __ldg(bT1 + s * IC + co);
        float b2 = __ldg(bT2 + s * IC + co);
        int o = base + co * TV;
        float2 p10 = unpack2(a10[co >> 1]);
        float2 p11 = unpack2(a11[co >> 1]);
        float2 p20 = unpack2(a20[co >> 1]);
        float2 p21 = unpack2(a21[co >> 1]);
        float v10 = (co & 1) ? p10.y : p10.x;
        float v11 = (co & 1) ? p11.y : p11.x;
        float v20 = (co & 1) ? p20.y : p20.x;
        float v21 = (co & 1) ? p21.y : p21.x;
        g_t1[o]      = sc * (v10 + b1);
        g_t1[o + VV] = sc * (v11 + b1);
        g_t2[o]      = sc * (v20 + b2);
        g_t2[o + VV] = sc * (v21 + b2);
    }
}

// ---------------------------------------------------------------------------
// K2: attention logits + softmax(axis=-2 over v1) + A_full -> A1  (unchanged)
// ---------------------------------------------------------------------------
__global__ __launch_bounds__(640, 2)
void k_att() {
    const int n = blockIdx.x;
    const int s = blockIdx.y;
    __shared__ float s1[64 * VV];
    __shared__ float s2[64 * VV];
    __shared__ float sl[VV * VV];

    const float* t1b = g_t1 + (size_t)(s * NB + n) * IC * TV;
    const float* t2b = g_t2 + (size_t)(s * NB + n) * IC * TV;

    const int tid = threadIdx.x;
    const int v1 = tid / 25;
    const int v2 = tid - v1 * 25;
    const bool act = tid < VV * VV;
    float acc = 0.f;

    for (int ch = 0; ch < KROWS / 64; ch++) {
        for (int idx = tid; idx < 64 * VV; idx += 640) {
            int row = idx / VV, vv = idx - row * VV;
            int cr = ch * 64 + row;
            int c = cr / TT, t = cr - c * TT;
            int off = c * TV + t * VV + vv;
            s1[idx] = t1b[off];
            s2[idx] = t2b[off];
        }
        __syncthreads();
        if (act) {
#pragma unroll 8
            for (int k = 0; k < 64; k++)
                acc += s1[k * VV + v1] * s2[k * VV + v2];
        }
        __syncthreads();
    }

    if (act) sl[tid] = acc * (1.0f / (float)KROWS);
    __syncthreads();

    if (tid < VV) {
        const int c2 = tid;
        float m = -1e30f;
#pragma unroll
        for (int r = 0; r < VV; r++) m = fmaxf(m, sl[r * VV + c2]);
        float sum = 0.f;
#pragma unroll
        for (int r = 0; r < VV; r++) sum += expf(sl[r * VV + c2] - m);
        float inv = 1.f / sum;
        const float* af = g_Afull + s * VV * VV;
        float* a1o = g_A1 + (size_t)(s * NB + n) * VV * VV;
#pragma unroll
        for (int r = 0; r < VV; r++)
            a1o[r * VV + c2] = af[r * VV + c2] + expf(sl[r * VV + c2] - m) * inv;
    }
}

// ---------------------------------------------------------------------------
// K3: agg + Wd fold + BN + residual + relu, f32x2 inner loops.
// grid: (30, N), block 256 (250 active, one (t,v2) each)
// ---------------------------------------------------------------------------
#define TT2 10
__global__ __launch_bounds__(256, 2)
void k_aggz(const float* __restrict__ x,
            const float* __restrict__ Wd, const float* __restrict__ bd,
            const float* __restrict__ weights,
            const float* __restrict__ bng, const float* __restrict__ bnb,
            const float* __restrict__ bnm, const float* __restrict__ bnv,
            float* __restrict__ out) {
    extern __shared__ float sm[];
    float* xs  = sm;              // 250*68 = 17000
    float* WdT = xs + 17000;      // 4096
    float* A1s = WdT + 4096;      // 625
    float* ka  = A1s + 625;       // 64
    float* kb  = ka + 64;         // 64

    const int n  = blockIdx.y;
    const int t0 = blockIdx.x * TT2;
    const int tid = threadIdx.x;
    const int nb = n * CCH * TV;

    for (int idx = tid; idx < CCH * TT2 * VV; idx += 256) {
        int ci = idx / (TT2 * VV);
        int tv = idx - ci * (TT2 * VV);
        xs[tv * 68 + ci] = x[nb + ci * TV + t0 * VV + tv];
    }
    if (tid < CCH) {
        int co = tid;
        float ws1 = weights[1], ws2 = weights[2], ws3 = weights[3], ws4 = weights[4];
        // slim splits for out_c=64: 38, 44, 51, 57
        float sc = (co < 38) ? 1.f : (co < 44) ? ws1 : (co < 51) ? ws2 : (co < 57) ? ws3 : ws4;
        float bdsum = bd[co] + bd[CCH + co] + bd[2 * CCH + co];
        float fa = bng[co] * rsqrtf(bnv[co] + 1e-5f);
        ka[co] = fa * sc;
        kb[co] = fa * sc * bdsum + bnb[co] - bnm[co] * fa;
    }

    // packed zacc: 32 co-pairs
    uint64_t zacc[32];
    const uint64_t z2 = pack2(0.f, 0.f);
#pragma unroll
    for (int i = 0; i < 32; i++) zacc[i] = z2;

    const int tv = tid;
    const bool act = tid < TT2 * VV;
    const int tloc = tv / 25;
    const int v2 = tv - tloc * 25;

    for (int s = 0; s < SS; s++) {
        __syncthreads();
        for (int idx = tid; idx < CCH * CCH; idx += 256) {
            int ci = idx >> 6;
            int co = idx & 63;
            WdT[ci * 64 + co] = Wd[(s * CCH + co) * CCH + ci];
        }
        for (int idx = tid; idx < VV * VV; idx += 256)
            A1s[idx] = g_A1[(size_t)(s * NB + n) * VV * VV + idx];
        __syncthreads();

        if (act) {
#pragma unroll
            for (int cb = 0; cb < 64; cb += 16) {
                // agg phase: 8 ci-pairs
                uint64_t ap[8];
#pragma unroll
                for (int i = 0; i < 8; i++) ap[i] = z2;
#pragma unroll
                for (int vv1 = 0; vv1 < VV; vv1++) {
                    float aw = A1s[vv1 * VV + v2];
                    uint64_t awp = pack2(aw, aw);
                    const ulonglong2* xp = (const ulonglong2*)(xs + (tloc * 25 + vv1) * 68 + cb);
#pragma unroll
                    for (int q = 0; q < 4; q++) {
                        ulonglong2 xv = xp[q];
                        fma2(ap[2*q],   xv.x, awp);
                        fma2(ap[2*q+1], xv.y, awp);
                    }
                }
                // fold phase: each agg value times its WdT row (packed co-pairs)
#pragma unroll
                for (int i = 0; i < 8; i++) {
                    float2 af = unpack2(ap[i]);
                    uint64_t av0 = pack2(af.x, af.x);
                    uint64_t av1 = pack2(af.y, af.y);
                    const ulonglong2* w0 = (const ulonglong2*)(WdT + (cb + 2*i) * 64);
                    const ulonglong2* w1 = (const ulonglong2*)(WdT + (cb + 2*i + 1) * 64);
#pragma unroll
                    for (int q = 0; q < 16; q++) {
                        ulonglong2 wv0 = w0[q];
                        fma2(zacc[2*q],   wv0.x, av0);
                        fma2(zacc[2*q+1], wv0.y, av0);
                    }
#pragma unroll
                    for (int q = 0; q < 16; q++) {
                        ulonglong2 wv1 = w1[q];
                        fma2(zacc[2*q],   wv1.x, av1);
                        fma2(zacc[2*q+1], wv1.y, av1);
                    }
                }
            }
        }
    }

    if (act) {
        const float* xrow = xs + (tloc * 25 + v2) * 68;
        const int ob = nb + t0 * VV + tv;
#pragma unroll
        for (int cp = 0; cp < 32; cp++) {
            float2 zz = unpack2(zacc[cp]);
            int c0 = 2 * cp, c1 = 2 * cp + 1;
            float val0 = ka[c0] * zz.x + kb[c0] + xrow[c0];
            float val1 = ka[c1] * zz.y + kb[c1] + xrow[c1];
            out[ob + c0 * TV] = fmaxf(val0, 0.f);
            out[ob + c1 * TV] = fmaxf(val1, 0.f);
        }
    }
}

// ---------------------------------------------------------------------------
// launch
// ---------------------------------------------------------------------------
extern "C" void kernel_launch(void* const* d_in, const int* in_sizes, int n_in,
                              void* d_out, int out_size) {
    const float* x    = (const float*)d_in[0];
    const float* wts  = (const float*)d_in[1];
    const float* A    = (const float*)d_in[2];
    const float* PA   = (const float*)d_in[3];
    const float* Wd   = (const float*)d_in[4];
    const float* bd   = (const float*)d_in[5];
    const float* WT1  = (const float*)d_in[6];
    const float* bT1  = (const float*)d_in[7];
    const float* WT2  = (const float*)d_in[8];
    const float* bT2  = (const float*)d_in[9];
    const float* bng  = (const float*)d_in[10];
    const float* bnb  = (const float*)d_in[11];
    const float* bnm  = (const float*)d_in[12];
    const float* bnv  = (const float*)d_in[13];
    float* out = (float*)d_out;

    const int conv_smem = 2 * IC * CCH * 9 * 4;           // 73728
    const int aggz_smem = (17000 + 4096 + 625 + 128) * 4; // 87396
    cudaFuncSetAttribute(k_conv, cudaFuncAttributeMaxDynamicSharedMemorySize, conv_smem);
    cudaFuncSetAttribute(k_aggz, cudaFuncAttributeMaxDynamicSharedMemorySize, aggz_smem);

    k_afull<<<1, 640>>>(A, PA);
    k_conv<<<dim3(10, NB, SS), 416, conv_smem>>>(x, WT1, bT1, WT2, bT2, wts);
    k_att<<<dim3(NB, SS), 640>>>();
    k_aggz<<<dim3(TT / TT2, NB), 256, aggz_smem>>>(x, Wd, bd, wts, bng, bnb, bnm, bnv, out);
}